// round 8
// baseline (speedup 1.0000x reference)
#include <cuda_runtime.h>

#define NQ     1224
#define NSTEPS 50
#define NB     1024
#define NROWS  (NB * (NSTEPS - 1))   // 50176 (b, t) pairs with t in [1, 49]
#define WARPS_PER_BLOCK 8

// Global double accumulator (allocation-free scratch).
__device__ double g_loss_sum;

__global__ void zero_kernel() { g_loss_sum = 0.0; }

// One warp per (b, t) row of `batch` (t >= 1). The 2448-wide row is an exact
// one-hot (one 1.0 in either the "correct" half [0,NQ) or the "incorrect"
// half [NQ,2NQ)). Scan both halves in lockstep with float4 loads; early-exit
// on the first nonzero via ballot. The hit column q gives the question index,
// and which half it landed in gives the label a. Then gather pred[b, t-1, q]
// and accumulate the BCE term. p = pred element is in (0,1) by construction,
// so the reference's `p > 0` mask is always satisfied on a hit; a row with no
// nonzero contributes 0, matching the masked reference.
__global__ __launch_bounds__(256) void dkt_loss_kernel(
    const float* __restrict__ pred,
    const float* __restrict__ batch)
{
    int warp = blockIdx.x * WARPS_PER_BLOCK + (threadIdx.x >> 5);
    int lane = threadIdx.x & 31;

    float contrib = 0.0f;

    if (warp < NROWS) {
        int b = warp / (NSTEPS - 1);
        int t = warp - b * (NSTEPS - 1) + 1;   // 1..49

        const float4* row1 = (const float4*)(batch + ((size_t)b * NSTEPS + t) * (size_t)(2 * NQ));
        const float4* row2 = row1 + (NQ / 4);  // second one-hot half
        const int NV = NQ / 4;                 // 306 float4 per half

        for (int base = 0; base < NV; base += 32) {
            int v = base + lane;
            float4 f = make_float4(0.f, 0.f, 0.f, 0.f);
            float4 s = make_float4(0.f, 0.f, 0.f, 0.f);
            if (v < NV) {
                f = __ldg(row1 + v);
                s = __ldg(row2 + v);
            }

            // Combined detection: exactly one of the 8 values can be nonzero.
            float cx = f.x + s.x, cy = f.y + s.y, cz = f.z + s.z, cw = f.w + s.w;

            int   q = -1;
            float a = 0.0f;
            if      (cx != 0.f) { q = 4 * v + 0; a = (f.x != 0.f) ? 1.0f : 0.0f; }
            else if (cy != 0.f) { q = 4 * v + 1; a = (f.y != 0.f) ? 1.0f : 0.0f; }
            else if (cz != 0.f) { q = 4 * v + 2; a = (f.z != 0.f) ? 1.0f : 0.0f; }
            else if (cw != 0.f) { q = 4 * v + 3; a = (f.w != 0.f) ? 1.0f : 0.0f; }

            unsigned m = __ballot_sync(0xffffffffu, q >= 0);
            if (m) {
                if (q >= 0) {
                    float p = __ldg(pred + ((size_t)b * NSTEPS + (t - 1)) * (size_t)NQ + q);
                    contrib = (a != 0.0f) ? logf(p) : logf(1.0f - p);
                }
                break;  // ballot result is warp-uniform -> no divergence hazard
            }
        }
    }

    // Warp reduction (at most one lane per warp is nonzero, but reduce anyway).
    #pragma unroll
    for (int o = 16; o; o >>= 1)
        contrib += __shfl_xor_sync(0xffffffffu, contrib, o);

    __shared__ float wsum[WARPS_PER_BLOCK];
    if (lane == 0) wsum[threadIdx.x >> 5] = contrib;
    __syncthreads();

    if (threadIdx.x == 0) {
        float blocksum = 0.0f;
        #pragma unroll
        for (int i = 0; i < WARPS_PER_BLOCK; i++) blocksum += wsum[i];
        atomicAdd(&g_loss_sum, (double)blocksum);
    }
}

__global__ void finalize_kernel(float* out) {
    out[0] = (float)(-g_loss_sum);
}

extern "C" void kernel_launch(void* const* d_in, const int* in_sizes, int n_in,
                              void* d_out, int out_size)
{
    // Identify inputs by element count (robust to metadata ordering):
    // pred  = 1024*50*1224 = 62,668,800
    // batch = 1024*50*2448 = 125,337,600
    const float* pred;
    const float* batch;
    if (in_sizes[0] == NB * NSTEPS * NQ) {
        pred  = (const float*)d_in[0];
        batch = (const float*)d_in[1];
    } else {
        pred  = (const float*)d_in[1];
        batch = (const float*)d_in[0];
    }

    zero_kernel<<<1, 1>>>();

    int blocks = (NROWS + WARPS_PER_BLOCK - 1) / WARPS_PER_BLOCK;  // 6272
    dkt_loss_kernel<<<blocks, 256>>>(pred, batch);

    finalize_kernel<<<1, 1>>>((float*)d_out);
}